// round 1
// baseline (speedup 1.0000x reference)
#include <cuda_runtime.h>
#include <math.h>

#define BB 8
#define CC 128
#define HH 160
#define WW 160
#define HW (HH*WW)
#define Hh 80
#define Wh 80

// ---------------- scratch (device globals; no allocation in kernel_launch) ----
__device__ float g_upflow[BB*2*HW];     // upsampled flow (2ch, 160x160)
__device__ float g_xin[BB*50*HW];       // 49 corr channels + 1 upsampled conf
__device__ float g_x1[BB*128*HW];
__device__ float g_x2[BB*64*HW];
__device__ float g_x3[BB*32*HW];

__device__ __forceinline__ float lrelu(float v) { return v > 0.f ? v : 0.1f * v; }

// ---------------- kernel 1: transposed-conv upsampling (flow 2ch + conf 1ch) --
__global__ void deconv_kernel(const float* __restrict__ flow,
                              const float* __restrict__ conf,
                              const float* __restrict__ wf,   // (2,1,4,4)
                              const float* __restrict__ wc)   // (1,1,4,4)
{
    int i = blockIdx.x * blockDim.x + threadIdx.x;
    if (i >= BB * 3 * HW) return;
    int x  = i % WW;
    int y  = (i / WW) % HH;
    int ch = (i / HW) % 3;
    int b  = i / (3 * HW);

    const float* w;
    const float* in;
    if (ch < 2) { w = wf + ch * 16; in = flow + (b * 2 + ch) * (Hh * Wh); }
    else        { w = wc;           in = conf + b * (Hh * Wh); }

    float acc = 0.f;
    #pragma unroll
    for (int ky = 0; ky < 4; ky++) {
        int t = y + 1 - ky;
        if (t & 1) continue;
        int iy = t >> 1;
        if ((unsigned)iy >= Hh) continue;
        #pragma unroll
        for (int kx = 0; kx < 4; kx++) {
            int u = x + 1 - kx;
            if (u & 1) continue;
            int ix = u >> 1;
            if ((unsigned)ix >= Wh) continue;
            acc += in[iy * Wh + ix] * w[ky * 4 + kx];
        }
    }
    if (ch < 2) g_upflow[(b * 2 + ch) * HW + y * WW + x] = acc;
    else        g_xin[((size_t)b * 50 + 49) * HW + y * WW + x] = acc;
}

// ---------------- kernel 2: 7x7 dilated self-correlation ---------------------
// block = 16x16 output tile; 4 channels per smem chunk; 49 register accumulators
__global__ __launch_bounds__(256) void corr_kernel(const float* __restrict__ feats)
{
    __shared__ float sm[4][28][48];   // 28x28 padded tile, stride 48 (conflict-free)
    int b   = blockIdx.z;
    int ty0 = blockIdx.y * 16, tx0 = blockIdx.x * 16;
    int tid = threadIdx.x;
    int lx  = tid & 15, ly = tid >> 4;

    const float* f = feats + (size_t)b * 2 * CC * HW;   // feats[:,0]

    float acc[49];
    #pragma unroll
    for (int d = 0; d < 49; d++) acc[d] = 0.f;

    for (int c0 = 0; c0 < CC; c0 += 4) {
        __syncthreads();
        for (int e = tid; e < 4 * 784; e += 256) {
            int cl = e / 784;
            int r  = (e % 784) / 28;
            int cc = e % 28;
            int gy = ty0 + r - 6, gx = tx0 + cc - 6;
            float v = 0.f;
            if ((unsigned)gy < HH && (unsigned)gx < WW)
                v = f[(size_t)(c0 + cl) * HW + gy * WW + gx];
            sm[cl][r][cc] = v;
        }
        __syncthreads();
        #pragma unroll
        for (int cl = 0; cl < 4; cl++) {
            float ctr = sm[cl][ly + 6][lx + 6];
            #pragma unroll
            for (int di = 0; di < 7; di++)
                #pragma unroll
                for (int dj = 0; dj < 7; dj++)
                    acc[di * 7 + dj] += ctr * sm[cl][ly + 2 * di][lx + 2 * dj];
        }
    }

    int y = ty0 + ly, x = tx0 + lx;
    float* out = g_xin + (size_t)b * 50 * HW + y * WW + x;
    #pragma unroll
    for (int d = 0; d < 49; d++)
        out[(size_t)d * HW] = lrelu(acc[d]) * (1.0f / 128.0f);
}

// ---------------- kernel 3: 3x3 conv + bias + lrelu --------------------------
// 32x32 spatial tile; thread = 4 px (x) * 8 oc; NIC input channels per chunk
template<int IC, int OC, int NIC>
__global__ __launch_bounds__(256) void conv3_kernel(const float* __restrict__ in,
                                                    const float* __restrict__ wt,
                                                    const float* __restrict__ bias,
                                                    float* __restrict__ out)
{
    constexpr int OCB = 8;
    __shared__ __align__(16) float tin[NIC][34][36];
    __shared__ float wsm[OCB][NIC][9];

    int tid = threadIdx.x;
    int tx = tid & 7;          // 0..7 -> 4 pixels each
    int ty = tid >> 3;         // 0..31
    int bx = blockIdx.x * 32, by = blockIdx.y * 32;
    int bz = blockIdx.z;
    int ocg = bz % (OC / OCB);
    int b   = bz / (OC / OCB);

    float acc[OCB][4];
    #pragma unroll
    for (int o = 0; o < OCB; o++) {
        #pragma unroll
        for (int j = 0; j < 4; j++) acc[o][j] = 0.f;
    }

    const float* inb = in + (size_t)b * IC * HW;

    for (int ic0 = 0; ic0 < IC; ic0 += NIC) {
        __syncthreads();
        for (int e = tid; e < NIC * 34 * 34; e += 256) {
            int cl = e / (34 * 34);
            int r  = (e / 34) % 34;
            int cc = e % 34;
            int gy = by + r - 1, gx = bx + cc - 1;
            float v = 0.f;
            if ((unsigned)gy < HH && (unsigned)gx < WW)
                v = inb[(size_t)(ic0 + cl) * HW + gy * WW + gx];
            tin[cl][r][cc] = v;
        }
        for (int e = tid; e < OCB * NIC * 9; e += 256) {
            int o = e / (NIC * 9);
            int rem = e % (NIC * 9);
            int cl = rem / 9, k = rem % 9;
            wsm[o][cl][k] = wt[((size_t)(ocg * OCB + o) * IC + (ic0 + cl)) * 9 + k];
        }
        __syncthreads();

        #pragma unroll
        for (int cl = 0; cl < NIC; cl++) {
            #pragma unroll
            for (int ky = 0; ky < 3; ky++) {
                const float* row = &tin[cl][ty + ky][0];
                float4 v4 = *(const float4*)(row + 4 * tx);
                float v0 = v4.x, v1 = v4.y, v2 = v4.z, v3 = v4.w;
                float v5 = row[4 * tx + 4];
                float v6 = row[4 * tx + 5];
                #pragma unroll
                for (int o = 0; o < OCB; o++) {
                    float w0 = wsm[o][cl][ky * 3 + 0];
                    float w1 = wsm[o][cl][ky * 3 + 1];
                    float w2 = wsm[o][cl][ky * 3 + 2];
                    acc[o][0] += v0 * w0 + v1 * w1 + v2 * w2;
                    acc[o][1] += v1 * w0 + v2 * w1 + v3 * w2;
                    acc[o][2] += v2 * w0 + v3 * w1 + v5 * w2;
                    acc[o][3] += v3 * w0 + v5 * w1 + v6 * w2;
                }
            }
        }
    }

    int y = by + ty, x = bx + 4 * tx;
    #pragma unroll
    for (int o = 0; o < OCB; o++) {
        float bv = bias[ocg * OCB + o];
        float4 r;
        r.x = lrelu(acc[o][0] + bv);
        r.y = lrelu(acc[o][1] + bv);
        r.z = lrelu(acc[o][2] + bv);
        r.w = lrelu(acc[o][3] + bv);
        *(float4*)(out + ((size_t)(b * OC + ocg * OCB + o) * HH + y) * WW + x) = r;
    }
}

// ---------------- kernel 4: 5x5 heads + warp + sigmoid -----------------------
__global__ __launch_bounds__(256) void head_kernel(const float* __restrict__ disp_w,
                                                   const float* __restrict__ disp_b,
                                                   const float* __restrict__ conf_w,
                                                   const float* __restrict__ conf_b,
                                                   float* __restrict__ out)
{
    __shared__ float sm[8][20][20];
    __shared__ float wsm[3][32][25];
    int tid = threadIdx.x;
    int lx = tid & 15, ly = tid >> 4;
    int b = blockIdx.z;
    int ty0 = blockIdx.y * 16, tx0 = blockIdx.x * 16;

    for (int e = tid; e < 3 * 32 * 25; e += 256) {
        int o = e / (32 * 25);
        int rem = e % (32 * 25);
        float v = (o < 2) ? disp_w[o * 32 * 25 + rem] : conf_w[rem];
        wsm[o][rem / 25][rem % 25] = v;
    }

    const float* x3 = g_x3 + (size_t)b * 32 * HW;
    float d0 = 0.f, d1 = 0.f, cf = 0.f;

    for (int c0 = 0; c0 < 32; c0 += 8) {
        __syncthreads();
        for (int e = tid; e < 8 * 400; e += 256) {
            int cl = e / 400;
            int r  = (e % 400) / 20;
            int cc = e % 20;
            int gy = ty0 + r - 2, gx = tx0 + cc - 2;
            float v = 0.f;
            if ((unsigned)gy < HH && (unsigned)gx < WW)
                v = x3[(size_t)(c0 + cl) * HW + gy * WW + gx];
            sm[cl][r][cc] = v;
        }
        __syncthreads();
        #pragma unroll
        for (int cl = 0; cl < 8; cl++) {
            int ic = c0 + cl;
            #pragma unroll
            for (int ky = 0; ky < 5; ky++) {
                #pragma unroll
                for (int kx = 0; kx < 5; kx++) {
                    float v = sm[cl][ly + ky][lx + kx];
                    int k = ky * 5 + kx;
                    d0 += v * wsm[0][ic][k];
                    d1 += v * wsm[1][ic][k];
                    cf += v * wsm[2][ic][k];
                }
            }
        }
    }
    d0 += disp_b[0];
    d1 += disp_b[1];
    cf += conf_b[0];

    int y = ty0 + ly, x = tx0 + lx;

    // ---- bilinear warp of g_upflow by (d0, d1), matching reference exactly ----
    const float* uf = g_upflow + (size_t)b * 2 * HW;
    float px = (float)x + d0;
    float py = (float)y + d1;
    float x0f = floorf(px), y0f = floorf(py);
    float wx1 = px - x0f, wx0 = 1.0f - wx1;
    float wy1 = py - y0f, wy0 = 1.0f - wy1;

    float v0c0, v0c1, v1c0, v1c1, v2c0, v2c1, v3c0, v3c1;
    float m0, m1, m2, m3;
    {
        float xs[4] = {x0f, x0f + 1.0f, x0f, x0f + 1.0f};
        float ys[4] = {y0f, y0f, y0f + 1.0f, y0f + 1.0f};
        float vc0[4], vc1[4], mm[4];
        #pragma unroll
        for (int q = 0; q < 4; q++) {
            float xi = xs[q], yi = ys[q];
            bool valid = (xi >= 0.f) && (xi <= (float)(WW - 1)) &&
                         (yi >= 0.f) && (yi <= (float)(HH - 1));
            float xc = fminf(fmaxf(xi, 0.f), (float)(WW - 1));
            float yc = fminf(fmaxf(yi, 0.f), (float)(HH - 1));
            int idx = (int)yc * WW + (int)xc;
            mm[q]  = valid ? 1.f : 0.f;
            vc0[q] = valid ? uf[idx] : 0.f;
            vc1[q] = valid ? uf[HW + idx] : 0.f;
        }
        v0c0 = vc0[0]; v1c0 = vc0[1]; v2c0 = vc0[2]; v3c0 = vc0[3];
        v0c1 = vc1[0]; v1c1 = vc1[1]; v2c1 = vc1[2]; v3c1 = vc1[3];
        m0 = mm[0]; m1 = mm[1]; m2 = mm[2]; m3 = mm[3];
    }
    float out0 = wy0 * (wx0 * v0c0 + wx1 * v1c0) + wy1 * (wx0 * v2c0 + wx1 * v3c0);
    float out1 = wy0 * (wx0 * v0c1 + wx1 * v1c1) + wy1 * (wx0 * v2c1 + wx1 * v3c1);
    float msk  = wy0 * (wx0 * m0 + wx1 * m1) + wy1 * (wx0 * m2 + wx1 * m3);
    float mask = (msk >= 1.0f) ? 1.f : 0.f;

    out[((size_t)(b * 2 + 0) * HH + y) * WW + x] = out0 * mask;
    out[((size_t)(b * 2 + 1) * HH + y) * WW + x] = out1 * mask;
    out[(size_t)BB * 2 * HW + ((size_t)b * HH + y) * WW + x] = 1.0f / (1.0f + expf(-cf));
}

// ---------------- launch -----------------------------------------------------
extern "C" void kernel_launch(void* const* d_in, const int* in_sizes, int n_in,
                              void* d_out, int out_size)
{
    const float* feats     = (const float*)d_in[0];
    const float* flow      = (const float*)d_in[1];
    const float* conf      = (const float*)d_in[2];
    const float* up_conf_w = (const float*)d_in[3];
    const float* up_flow_w = (const float*)d_in[4];
    const float* w1        = (const float*)d_in[5];
    const float* b1        = (const float*)d_in[6];
    const float* w2        = (const float*)d_in[7];
    const float* b2        = (const float*)d_in[8];
    const float* w3        = (const float*)d_in[9];
    const float* b3        = (const float*)d_in[10];
    const float* disp_w    = (const float*)d_in[11];
    const float* disp_b    = (const float*)d_in[12];
    const float* conf_w    = (const float*)d_in[13];
    const float* conf_b    = (const float*)d_in[14];
    float* out = (float*)d_out;

    float *xin, *x1, *x2, *x3;
    cudaGetSymbolAddress((void**)&xin, g_xin);
    cudaGetSymbolAddress((void**)&x1,  g_x1);
    cudaGetSymbolAddress((void**)&x2,  g_x2);
    cudaGetSymbolAddress((void**)&x3,  g_x3);

    deconv_kernel<<<(BB * 3 * HW + 255) / 256, 256>>>(flow, conf, up_flow_w, up_conf_w);
    corr_kernel<<<dim3(10, 10, BB), 256>>>(feats);
    conv3_kernel<50, 128, 5><<<dim3(5, 5, BB * 16), 256>>>(xin, w1, b1, x1);
    conv3_kernel<128, 64, 4><<<dim3(5, 5, BB * 8),  256>>>(x1, w2, b2, x2);
    conv3_kernel<64, 32, 4><<<dim3(5, 5, BB * 4),  256>>>(x2, w3, b3, x3);
    head_kernel<<<dim3(10, 10, BB), 256>>>(disp_w, disp_b, conf_w, conf_b, out);
}

// round 3
// speedup vs baseline: 1.0298x; 1.0298x over previous
#include <cuda_runtime.h>
#include <math.h>

#define BB 8
#define CC 128
#define HH 160
#define WW 160
#define HW (HH*WW)
#define Hh 80
#define Wh 80

typedef unsigned long long ull;

// ---------------- scratch (device globals; no allocation in kernel_launch) ----
__device__ float g_upflow[BB*2*HW];     // upsampled flow (2ch, 160x160)
__device__ float g_xin[BB*50*HW];       // 49 corr channels + 1 upsampled conf
__device__ float g_x1[BB*128*HW];
__device__ float g_x2[BB*64*HW];
__device__ float g_x3[BB*32*HW];

__device__ __forceinline__ float lrelu(float v) { return v > 0.f ? v : 0.1f * v; }

// packed fp32x2 helpers (Blackwell FFMA2 path — ptxas won't emit from C++)
__device__ __forceinline__ void fma2(ull &d, ull a, ull b) {
    asm("fma.rn.f32x2 %0, %1, %2, %0;" : "+l"(d) : "l"(a), "l"(b));
}
__device__ __forceinline__ ull pk(float lo, float hi) {
    ull r;
    asm("mov.b64 %0, {%1, %2};" : "=l"(r) : "f"(lo), "f"(hi));
    return r;
}
__device__ __forceinline__ void upk(float &lo, float &hi, ull p) {
    asm("mov.b64 {%0, %1}, %2;" : "=f"(lo), "=f"(hi) : "l"(p));
}

// ---------------- kernel 1: transposed-conv upsampling (flow 2ch + conf 1ch) --
__global__ void deconv_kernel(const float* __restrict__ flow,
                              const float* __restrict__ conf,
                              const float* __restrict__ wf,   // (2,1,4,4)
                              const float* __restrict__ wc)   // (1,1,4,4)
{
    int i = blockIdx.x * blockDim.x + threadIdx.x;
    if (i >= BB * 3 * HW) return;
    int x  = i % WW;
    int y  = (i / WW) % HH;
    int ch = (i / HW) % 3;
    int b  = i / (3 * HW);

    const float* w;
    const float* in;
    if (ch < 2) { w = wf + ch * 16; in = flow + (b * 2 + ch) * (Hh * Wh); }
    else        { w = wc;           in = conf + b * (Hh * Wh); }

    float acc = 0.f;
    #pragma unroll
    for (int ky = 0; ky < 4; ky++) {
        int t = y + 1 - ky;
        if (t & 1) continue;
        int iy = t >> 1;
        if ((unsigned)iy >= Hh) continue;
        #pragma unroll
        for (int kx = 0; kx < 4; kx++) {
            int u = x + 1 - kx;
            if (u & 1) continue;
            int ix = u >> 1;
            if ((unsigned)ix >= Wh) continue;
            acc += in[iy * Wh + ix] * w[ky * 4 + kx];
        }
    }
    if (ch < 2) g_upflow[(b * 2 + ch) * HW + y * WW + x] = acc;
    else        g_xin[((size_t)b * 50 + 49) * HW + y * WW + x] = acc;
}

// ---------------- kernel 2: 7x7 dilated self-correlation ---------------------
__global__ __launch_bounds__(256) void corr_kernel(const float* __restrict__ feats)
{
    __shared__ float sm[4][28][48];
    int b   = blockIdx.z;
    int ty0 = blockIdx.y * 16, tx0 = blockIdx.x * 16;
    int tid = threadIdx.x;
    int lx  = tid & 15, ly = tid >> 4;

    const float* f = feats + (size_t)b * 2 * CC * HW;   // feats[:,0]

    float acc[49];
    #pragma unroll
    for (int d = 0; d < 49; d++) acc[d] = 0.f;

    for (int c0 = 0; c0 < CC; c0 += 4) {
        __syncthreads();
        for (int e = tid; e < 4 * 784; e += 256) {
            int cl = e / 784;
            int r  = (e % 784) / 28;
            int cc = e % 28;
            int gy = ty0 + r - 6, gx = tx0 + cc - 6;
            float v = 0.f;
            if ((unsigned)gy < HH && (unsigned)gx < WW)
                v = f[(size_t)(c0 + cl) * HW + gy * WW + gx];
            sm[cl][r][cc] = v;
        }
        __syncthreads();
        #pragma unroll
        for (int cl = 0; cl < 4; cl++) {
            float ctr = sm[cl][ly + 6][lx + 6];
            #pragma unroll
            for (int di = 0; di < 7; di++)
                #pragma unroll
                for (int dj = 0; dj < 7; dj++)
                    acc[di * 7 + dj] += ctr * sm[cl][ly + 2 * di][lx + 2 * dj];
        }
    }

    int y = ty0 + ly, x = tx0 + lx;
    float* out = g_xin + (size_t)b * 50 * HW + y * WW + x;
    #pragma unroll
    for (int d = 0; d < 49; d++)
        out[(size_t)d * HW] = lrelu(acc[d]) * (1.0f / 128.0f);
}

// ---------------- kernel 3: 3x3 conv + bias + lrelu, packed f32x2 ------------
// 32x32 spatial tile; 256 threads: 4 tx (8 px each) x 32 ty x 2 oc-groups(8 oc)
// Each thread: 8 oc x 4 pixel-pair f32x2 accumulators.
template<int IC, int OC, int NIC>
__global__ __launch_bounds__(256) void conv3_kernel(const float* __restrict__ in,
                                                    const float* __restrict__ wt,
                                                    const float* __restrict__ bias,
                                                    float* __restrict__ out)
{
    __shared__ __align__(16) float tin[NIC][34][40];
    __shared__ ull wsm[16][NIC][9];   // weights duplicated (w,w)

    int tid = threadIdx.x;
    int tx = tid & 3;            // 0..3 -> 8 pixels each
    int ty = (tid >> 2) & 31;    // 0..31
    int og = tid >> 7;           // 0..1 (8-oc group within block)
    int bx = blockIdx.x * 32, by = blockIdx.y * 32;
    int bz = blockIdx.z;
    int ocg = bz % (OC / 16);
    int b   = bz / (OC / 16);

    ull acc[8][4];
    #pragma unroll
    for (int o = 0; o < 8; o++)
        #pragma unroll
        for (int p = 0; p < 4; p++) acc[o][p] = 0ull;

    const float* inb = in + (size_t)b * IC * HW;

    for (int ic0 = 0; ic0 < IC; ic0 += NIC) {
        __syncthreads();
        for (int e = tid; e < NIC * 34 * 34; e += 256) {
            int cl = e / (34 * 34);
            int r  = (e / 34) % 34;
            int cc = e % 34;
            int gy = by + r - 1, gx = bx + cc - 1;
            float v = 0.f;
            if ((unsigned)gy < HH && (unsigned)gx < WW)
                v = inb[(size_t)(ic0 + cl) * HW + gy * WW + gx];
            tin[cl][r][cc] = v;
        }
        for (int e = tid; e < 16 * NIC * 9; e += 256) {
            int o = e / (NIC * 9);
            int rem = e % (NIC * 9);
            int cl = rem / 9, k = rem % 9;
            float w = wt[((size_t)(ocg * 16 + o) * IC + (ic0 + cl)) * 9 + k];
            wsm[o][cl][k] = pk(w, w);
        }
        __syncthreads();

        #pragma unroll
        for (int cl = 0; cl < NIC; cl++) {
            #pragma unroll
            for (int ky = 0; ky < 3; ky++) {
                const float* row = &tin[cl][ty + ky][8 * tx];
                float4 va = *(const float4*)row;       // v0..v3
                float4 vb = *(const float4*)(row + 4); // v4..v7
                float v8 = row[8], v9 = row[9];
                ull q[9];
                q[0] = pk(va.x, va.y);
                q[1] = pk(va.y, va.z);
                q[2] = pk(va.z, va.w);
                q[3] = pk(va.w, vb.x);
                q[4] = pk(vb.x, vb.y);
                q[5] = pk(vb.y, vb.z);
                q[6] = pk(vb.z, vb.w);
                q[7] = pk(vb.w, v8);
                q[8] = pk(v8, v9);
                #pragma unroll
                for (int o = 0; o < 8; o++) {
                    const ull* wp = &wsm[og * 8 + o][cl][ky * 3];
                    ull w0 = wp[0], w1 = wp[1], w2 = wp[2];
                    #pragma unroll
                    for (int p = 0; p < 4; p++) {
                        fma2(acc[o][p], q[2 * p],     w0);
                        fma2(acc[o][p], q[2 * p + 1], w1);
                        fma2(acc[o][p], q[2 * p + 2], w2);
                    }
                }
            }
        }
    }

    int y = by + ty, x = bx + 8 * tx;
    #pragma unroll
    for (int o = 0; o < 8; o++) {
        int oc = ocg * 16 + og * 8 + o;
        float bv = bias[oc];
        float r[8];
        #pragma unroll
        for (int p = 0; p < 4; p++) {
            float lo, hi;
            upk(lo, hi, acc[o][p]);
            r[2 * p]     = lrelu(lo + bv);
            r[2 * p + 1] = lrelu(hi + bv);
        }
        float* op = out + ((size_t)(b * OC + oc) * HH + y) * WW + x;
        *(float4*)op       = make_float4(r[0], r[1], r[2], r[3]);
        *(float4*)(op + 4) = make_float4(r[4], r[5], r[6], r[7]);
    }
}

// ---------------- kernel 4: 5x5 heads + warp + sigmoid -----------------------
__global__ __launch_bounds__(256) void head_kernel(const float* __restrict__ disp_w,
                                                   const float* __restrict__ disp_b,
                                                   const float* __restrict__ conf_w,
                                                   const float* __restrict__ conf_b,
                                                   float* __restrict__ out)
{
    __shared__ float sm[8][20][20];
    __shared__ float wsm[3][32][25];
    int tid = threadIdx.x;
    int lx = tid & 15, ly = tid >> 4;
    int b = blockIdx.z;
    int ty0 = blockIdx.y * 16, tx0 = blockIdx.x * 16;

    for (int e = tid; e < 3 * 32 * 25; e += 256) {
        int o = e / (32 * 25);
        int rem = e % (32 * 25);
        float v = (o < 2) ? disp_w[o * 32 * 25 + rem] : conf_w[rem];
        wsm[o][rem / 25][rem % 25] = v;
    }

    const float* x3 = g_x3 + (size_t)b * 32 * HW;
    float d0 = 0.f, d1 = 0.f, cf = 0.f;

    for (int c0 = 0; c0 < 32; c0 += 8) {
        __syncthreads();
        for (int e = tid; e < 8 * 400; e += 256) {
            int cl = e / 400;
            int r  = (e % 400) / 20;
            int cc = e % 20;
            int gy = ty0 + r - 2, gx = tx0 + cc - 2;
            float v = 0.f;
            if ((unsigned)gy < HH && (unsigned)gx < WW)
                v = x3[(size_t)(c0 + cl) * HW + gy * WW + gx];
            sm[cl][r][cc] = v;
        }
        __syncthreads();
        #pragma unroll
        for (int cl = 0; cl < 8; cl++) {
            int ic = c0 + cl;
            #pragma unroll
            for (int ky = 0; ky < 5; ky++) {
                #pragma unroll
                for (int kx = 0; kx < 5; kx++) {
                    float v = sm[cl][ly + ky][lx + kx];
                    int k = ky * 5 + kx;
                    d0 += v * wsm[0][ic][k];
                    d1 += v * wsm[1][ic][k];
                    cf += v * wsm[2][ic][k];
                }
            }
        }
    }
    d0 += disp_b[0];
    d1 += disp_b[1];
    cf += conf_b[0];

    int y = ty0 + ly, x = tx0 + lx;

    // ---- bilinear warp of g_upflow by (d0, d1), matching reference exactly ----
    const float* uf = g_upflow + (size_t)b * 2 * HW;
    float px = (float)x + d0;
    float py = (float)y + d1;
    float x0f = floorf(px), y0f = floorf(py);
    float wx1 = px - x0f, wx0 = 1.0f - wx1;
    float wy1 = py - y0f, wy0 = 1.0f - wy1;

    float vc0[4], vc1[4], mm[4];
    float xs[4] = {x0f, x0f + 1.0f, x0f, x0f + 1.0f};
    float ys[4] = {y0f, y0f, y0f + 1.0f, y0f + 1.0f};
    #pragma unroll
    for (int q = 0; q < 4; q++) {
        float xi = xs[q], yi = ys[q];
        bool valid = (xi >= 0.f) && (xi <= (float)(WW - 1)) &&
                     (yi >= 0.f) && (yi <= (float)(HH - 1));
        float xc = fminf(fmaxf(xi, 0.f), (float)(WW - 1));
        float yc = fminf(fmaxf(yi, 0.f), (float)(HH - 1));
        int idx = (int)yc * WW + (int)xc;
        mm[q]  = valid ? 1.f : 0.f;
        vc0[q] = valid ? uf[idx] : 0.f;
        vc1[q] = valid ? uf[HW + idx] : 0.f;
    }
    float out0 = wy0 * (wx0 * vc0[0] + wx1 * vc0[1]) + wy1 * (wx0 * vc0[2] + wx1 * vc0[3]);
    float out1 = wy0 * (wx0 * vc1[0] + wx1 * vc1[1]) + wy1 * (wx0 * vc1[2] + wx1 * vc1[3]);
    float msk  = wy0 * (wx0 * mm[0] + wx1 * mm[1]) + wy1 * (wx0 * mm[2] + wx1 * mm[3]);
    float mask = (msk >= 1.0f) ? 1.f : 0.f;

    out[((size_t)(b * 2 + 0) * HH + y) * WW + x] = out0 * mask;
    out[((size_t)(b * 2 + 1) * HH + y) * WW + x] = out1 * mask;
    out[(size_t)BB * 2 * HW + ((size_t)b * HH + y) * WW + x] = 1.0f / (1.0f + expf(-cf));
}

// ---------------- launch -----------------------------------------------------
extern "C" void kernel_launch(void* const* d_in, const int* in_sizes, int n_in,
                              void* d_out, int out_size)
{
    const float* feats     = (const float*)d_in[0];
    const float* flow      = (const float*)d_in[1];
    const float* conf      = (const float*)d_in[2];
    const float* up_conf_w = (const float*)d_in[3];
    const float* up_flow_w = (const float*)d_in[4];
    const float* w1        = (const float*)d_in[5];
    const float* b1        = (const float*)d_in[6];
    const float* w2        = (const float*)d_in[7];
    const float* b2        = (const float*)d_in[8];
    const float* w3        = (const float*)d_in[9];
    const float* b3        = (const float*)d_in[10];
    const float* disp_w    = (const float*)d_in[11];
    const float* disp_b    = (const float*)d_in[12];
    const float* conf_w    = (const float*)d_in[13];
    const float* conf_b    = (const float*)d_in[14];
    float* out = (float*)d_out;

    float *xin, *x1, *x2, *x3;
    cudaGetSymbolAddress((void**)&xin, g_xin);
    cudaGetSymbolAddress((void**)&x1,  g_x1);
    cudaGetSymbolAddress((void**)&x2,  g_x2);
    cudaGetSymbolAddress((void**)&x3,  g_x3);

    deconv_kernel<<<(BB * 3 * HW + 255) / 256, 256>>>(flow, conf, up_flow_w, up_conf_w);
    corr_kernel<<<dim3(10, 10, BB), 256>>>(feats);
    conv3_kernel<50, 128, 5><<<dim3(5, 5, BB * 8), 256>>>(xin, w1, b1, x1);
    conv3_kernel<128, 64, 4><<<dim3(5, 5, BB * 4), 256>>>(x1, w2, b2, x2);
    conv3_kernel<64, 32, 4><<<dim3(5, 5, BB * 2), 256>>>(x2, w3, b3, x3);
    head_kernel<<<dim3(10, 10, BB), 256>>>(disp_w, disp_b, conf_w, conf_b, out);
}

// round 5
// speedup vs baseline: 1.1519x; 1.1185x over previous
#include <cuda_runtime.h>
#include <math.h>

#define BB 8
#define CC 128
#define HH 160
#define WW 160
#define HW (HH*WW)
#define Hh 80
#define Wh 80

typedef unsigned long long ull;

// ---------------- scratch (device globals; no allocation in kernel_launch) ----
__device__ float g_upflow[BB*2*HW];     // upsampled flow (2ch, 160x160)
__device__ float g_xin[BB*50*HW];       // 49 corr channels + 1 upsampled conf
__device__ float g_x1[BB*128*HW];
__device__ float g_x2[BB*64*HW];
__device__ float g_x3[BB*32*HW];

__device__ __forceinline__ float lrelu(float v) { return v > 0.f ? v : 0.1f * v; }

// packed fp32x2 helpers
__device__ __forceinline__ void fma2(ull &d, ull a, ull b) {
    asm("fma.rn.f32x2 %0, %1, %2, %0;" : "+l"(d) : "l"(a), "l"(b));
}
__device__ __forceinline__ ull pk(float lo, float hi) {
    ull r;
    asm("mov.b64 %0, {%1, %2};" : "=l"(r) : "f"(lo), "f"(hi));
    return r;
}
__device__ __forceinline__ void upk(float &lo, float &hi, ull p) {
    asm("mov.b64 {%0, %1}, %2;" : "=f"(lo), "=f"(hi) : "l"(p));
}

// cp.async helpers (4B with zero-fill on out-of-bounds)
__device__ __forceinline__ unsigned su(const void* p) {
    return (unsigned)__cvta_generic_to_shared(p);
}
__device__ __forceinline__ void cpa4(unsigned dst, const float* src, bool v) {
    int sz = v ? 4 : 0;
    asm volatile("cp.async.ca.shared.global [%0], [%1], 4, %2;" :: "r"(dst), "l"(src), "r"(sz));
}
#define CPCOMMIT asm volatile("cp.async.commit_group;")
#define CPWAIT(N) asm volatile("cp.async.wait_group %0;" :: "n"(N))

// ---------------- kernel 1: transposed-conv upsampling (flow 2ch + conf 1ch) --
__global__ void deconv_kernel(const float* __restrict__ flow,
                              const float* __restrict__ conf,
                              const float* __restrict__ wf,   // (2,1,4,4)
                              const float* __restrict__ wc)   // (1,1,4,4)
{
    int i = blockIdx.x * blockDim.x + threadIdx.x;
    if (i >= BB * 3 * HW) return;
    int x  = i % WW;
    int y  = (i / WW) % HH;
    int ch = (i / HW) % 3;
    int b  = i / (3 * HW);

    const float* w;
    const float* in;
    if (ch < 2) { w = wf + ch * 16; in = flow + (b * 2 + ch) * (Hh * Wh); }
    else        { w = wc;           in = conf + b * (Hh * Wh); }

    float acc = 0.f;
    #pragma unroll
    for (int ky = 0; ky < 4; ky++) {
        int t = y + 1 - ky;
        if (t & 1) continue;
        int iy = t >> 1;
        if ((unsigned)iy >= Hh) continue;
        #pragma unroll
        for (int kx = 0; kx < 4; kx++) {
            int u = x + 1 - kx;
            if (u & 1) continue;
            int ix = u >> 1;
            if ((unsigned)ix >= Wh) continue;
            acc += in[iy * Wh + ix] * w[ky * 4 + kx];
        }
    }
    if (ch < 2) g_upflow[(b * 2 + ch) * HW + y * WW + x] = acc;
    else        g_xin[((size_t)b * 50 + 49) * HW + y * WW + x] = acc;
}

// ---------------- kernel 2: 7x7 dilated self-correlation, packed over ch pairs
// 512 threads: 16x16 px tile x 2 offset-halves (25/25 offsets, overlap at 24)
__global__ __launch_bounds__(512) void corr_kernel(const float* __restrict__ feats)
{
    __shared__ float2 sm2[2][2][28][32];   // [buf][chpair][row][col]
    int b   = blockIdx.z;
    int ty0 = blockIdx.y * 16, tx0 = blockIdx.x * 16;
    int tid = threadIdx.x;
    int lx  = tid & 15, ly = (tid >> 4) & 15, hd = tid >> 8;

    const float* f = feats + (size_t)b * 2 * CC * HW;   // feats[:,0]

    ull acc2[25];
    #pragma unroll
    for (int d = 0; d < 25; d++) acc2[d] = 0ull;

    auto pre = [&](int c0, int s) {
        for (int e = tid; e < 4 * 28 * 28; e += 512) {
            int c  = e / 784;
            int rm = e - c * 784;
            int r  = rm / 28;
            int cc = rm - r * 28;
            int gy = ty0 + r - 6, gx = tx0 + cc - 6;
            bool v = ((unsigned)gy < HH) && ((unsigned)gx < WW);
            int cy = v ? gy : 0, cx = v ? gx : 0;
            float* dst = (float*)&sm2[s][c >> 1][r][cc] + (c & 1);
            cpa4(su(dst), f + (size_t)(c0 + c) * HW + cy * WW + cx, v);
        }
    };

    pre(0, 0); CPCOMMIT;
    for (int ch = 0; ch < 32; ch++) {
        int s = ch & 1;
        if (ch < 31) { pre((ch + 1) * 4, s ^ 1); CPCOMMIT; CPWAIT(1); }
        else         { CPWAIT(0); }
        __syncthreads();
        #pragma unroll
        for (int pr = 0; pr < 2; pr++) {
            ull ctr = *(const ull*)&sm2[s][pr][ly + 6][lx + 6];
            if (hd == 0) {
                #pragma unroll
                for (int d = 0; d < 25; d++) {
                    int di = d / 7, dj = d % 7;
                    ull t = *(const ull*)&sm2[s][pr][ly + 2 * di][lx + 2 * dj];
                    fma2(acc2[d], ctr, t);
                }
            } else {
                #pragma unroll
                for (int d = 0; d < 25; d++) {
                    int di = (24 + d) / 7, dj = (24 + d) % 7;
                    ull t = *(const ull*)&sm2[s][pr][ly + 2 * di][lx + 2 * dj];
                    fma2(acc2[d], ctr, t);
                }
            }
        }
        __syncthreads();
    }

    int y = ty0 + ly, x = tx0 + lx;
    float* out = g_xin + (size_t)b * 50 * HW + y * WW + x;
    int D0 = hd * 24;
    #pragma unroll
    for (int d = 0; d < 25; d++) {
        float lo, hi;
        upk(lo, hi, acc2[d]);
        out[(size_t)(D0 + d) * HW] = lrelu(lo + hi) * (1.0f / 128.0f);
    }
}

// ---------------- kernel 3: 3x3 conv + bias + lrelu, f32x2 + cp.async DB -----
// 32x32 tile; 256 threads: 2 tx (16 px each) x 32 ty x 4 og (4 oc each)
template<int IC, int OC, int NIC>
__global__ __launch_bounds__(256, 2) void conv3_kernel(const float* __restrict__ in,
                                                       const float* __restrict__ wt,
                                                       const float* __restrict__ bias,
                                                       float* __restrict__ out)
{
    constexpr int NCH  = IC / NIC;
    constexpr int WTOT = 16 * NIC * 9;
    constexpr int NW   = (WTOT + 255) / 256;
    __shared__ __align__(16) float tin[2][NIC][34][36];
    __shared__ ull wsm[2][16][NIC][9];

    int tid = threadIdx.x;
    int tx = tid & 1;
    int ty = (tid >> 1) & 31;
    int og = tid >> 6;               // 0..3
    int bx = blockIdx.x * 32, by = blockIdx.y * 32;
    int bz = blockIdx.z;
    int ocg = bz % (OC / 16);
    int b   = bz / (OC / 16);

    ull acc[4][8];
    #pragma unroll
    for (int o = 0; o < 4; o++)
        #pragma unroll
        for (int p = 0; p < 8; p++) acc[o][p] = 0ull;

    const float* inb = in + (size_t)b * IC * HW;
    const float* wtb = wt + (size_t)(ocg * 16) * IC * 9;

    auto pre_tile = [&](int ic0, int s) {
        for (int e = tid; e < NIC * 34 * 34; e += 256) {
            int cl = e / (34 * 34);
            int rm = e - cl * 34 * 34;
            int r  = rm / 34;
            int cc = rm - r * 34;
            int gy = by + r - 1, gx = bx + cc - 1;
            bool v = ((unsigned)gy < HH) && ((unsigned)gx < WW);
            int cy = v ? gy : 0, cx = v ? gx : 0;
            cpa4(su(&tin[s][cl][r][cc]), inb + (size_t)(ic0 + cl) * HW + cy * WW + cx, v);
        }
    };

    float wreg[NW];
    auto ldw = [&](int ic0) {
        #pragma unroll
        for (int j = 0; j < NW; j++) {
            int e = tid + j * 256;
            if (e < WTOT) {
                int o = e / (NIC * 9);
                int rem = e - o * NIC * 9;
                int cl = rem / 9, k = rem - cl * 9;
                wreg[j] = wtb[(size_t)o * IC * 9 + (size_t)(ic0 + cl) * 9 + k];
            }
        }
    };
    auto stw = [&](int s) {
        #pragma unroll
        for (int j = 0; j < NW; j++) {
            int e = tid + j * 256;
            if (e < WTOT) {
                int o = e / (NIC * 9);
                int rem = e - o * NIC * 9;
                int cl = rem / 9, k = rem - cl * 9;
                wsm[s][o][cl][k] = pk(wreg[j], wreg[j]);
            }
        }
    };

    pre_tile(0, 0); CPCOMMIT;
    ldw(0); stw(0);

    for (int ch = 0; ch < NCH; ch++) {
        int s = ch & 1;
        if (ch + 1 < NCH) {
            pre_tile((ch + 1) * NIC, s ^ 1); CPCOMMIT;
            ldw((ch + 1) * NIC);
            CPWAIT(1);
        } else {
            CPWAIT(0);
        }
        __syncthreads();

        #pragma unroll
        for (int cl = 0; cl < NIC; cl++) {
            #pragma unroll
            for (int ky = 0; ky < 3; ky++) {
                const float* row = &tin[s][cl][ty + ky][16 * tx];
                float4 a0 = *(const float4*)(row);
                float4 a1 = *(const float4*)(row + 4);
                float4 a2 = *(const float4*)(row + 8);
                float4 a3 = *(const float4*)(row + 12);
                float e0 = row[16], e1 = row[17];
                ull q[17];
                q[0]  = pk(a0.x, a0.y); q[1]  = pk(a0.y, a0.z); q[2]  = pk(a0.z, a0.w); q[3]  = pk(a0.w, a1.x);
                q[4]  = pk(a1.x, a1.y); q[5]  = pk(a1.y, a1.z); q[6]  = pk(a1.z, a1.w); q[7]  = pk(a1.w, a2.x);
                q[8]  = pk(a2.x, a2.y); q[9]  = pk(a2.y, a2.z); q[10] = pk(a2.z, a2.w); q[11] = pk(a2.w, a3.x);
                q[12] = pk(a3.x, a3.y); q[13] = pk(a3.y, a3.z); q[14] = pk(a3.z, a3.w); q[15] = pk(a3.w, e0);
                q[16] = pk(e0, e1);
                #pragma unroll
                for (int o = 0; o < 4; o++) {
                    const ull* wp = &wsm[s][og * 4 + o][cl][ky * 3];
                    ull w0 = wp[0], w1 = wp[1], w2 = wp[2];
                    #pragma unroll
                    for (int p = 0; p < 8; p++) {
                        fma2(acc[o][p], q[2 * p],     w0);
                        fma2(acc[o][p], q[2 * p + 1], w1);
                        fma2(acc[o][p], q[2 * p + 2], w2);
                    }
                }
            }
        }
        if (ch + 1 < NCH) stw(s ^ 1);
        __syncthreads();
    }

    int y = by + ty, xb = bx + 16 * tx;
    #pragma unroll
    for (int o = 0; o < 4; o++) {
        int oc = ocg * 16 + og * 4 + o;
        float bv = bias[oc];
        float r[16];
        #pragma unroll
        for (int p = 0; p < 8; p++) {
            float lo, hi;
            upk(lo, hi, acc[o][p]);
            r[2 * p]     = lrelu(lo + bv);
            r[2 * p + 1] = lrelu(hi + bv);
        }
        float* op = out + ((size_t)(b * OC + oc) * HH + y) * WW + xb;
        *(float4*)(op)      = make_float4(r[0],  r[1],  r[2],  r[3]);
        *(float4*)(op + 4)  = make_float4(r[4],  r[5],  r[6],  r[7]);
        *(float4*)(op + 8)  = make_float4(r[8],  r[9],  r[10], r[11]);
        *(float4*)(op + 12) = make_float4(r[12], r[13], r[14], r[15]);
    }
}

// ---------------- kernel 4: 5x5 heads + warp + sigmoid -----------------------
__global__ __launch_bounds__(256) void head_kernel(const float* __restrict__ disp_w,
                                                   const float* __restrict__ disp_b,
                                                   const float* __restrict__ conf_w,
                                                   const float* __restrict__ conf_b,
                                                   float* __restrict__ out)
{
    __shared__ float sm[8][20][20];
    __shared__ float wsm[3][32][25];
    int tid = threadIdx.x;
    int lx = tid & 15, ly = tid >> 4;
    int b = blockIdx.z;
    int ty0 = blockIdx.y * 16, tx0 = blockIdx.x * 16;

    for (int e = tid; e < 3 * 32 * 25; e += 256) {
        int o = e / (32 * 25);
        int rem = e % (32 * 25);
        float v = (o < 2) ? disp_w[o * 32 * 25 + rem] : conf_w[rem];
        wsm[o][rem / 25][rem % 25] = v;
    }

    const float* x3 = g_x3 + (size_t)b * 32 * HW;
    float d0 = 0.f, d1 = 0.f, cf = 0.f;

    for (int c0 = 0; c0 < 32; c0 += 8) {
        __syncthreads();
        for (int e = tid; e < 8 * 400; e += 256) {
            int cl = e / 400;
            int r  = (e % 400) / 20;
            int cc = e % 20;
            int gy = ty0 + r - 2, gx = tx0 + cc - 2;
            float v = 0.f;
            if ((unsigned)gy < HH && (unsigned)gx < WW)
                v = x3[(size_t)(c0 + cl) * HW + gy * WW + gx];
            sm[cl][r][cc] = v;
        }
        __syncthreads();
        #pragma unroll
        for (int cl = 0; cl < 8; cl++) {
            int ic = c0 + cl;
            #pragma unroll
            for (int ky = 0; ky < 5; ky++) {
                #pragma unroll
                for (int kx = 0; kx < 5; kx++) {
                    float v = sm[cl][ly + ky][lx + kx];
                    int k = ky * 5 + kx;
                    d0 += v * wsm[0][ic][k];
                    d1 += v * wsm[1][ic][k];
                    cf += v * wsm[2][ic][k];
                }
            }
        }
    }
    d0 += disp_b[0];
    d1 += disp_b[1];
    cf += conf_b[0];

    int y = ty0 + ly, x = tx0 + lx;

    // ---- bilinear warp of g_upflow by (d0, d1), matching reference exactly ----
    const float* uf = g_upflow + (size_t)b * 2 * HW;
    float px = (float)x + d0;
    float py = (float)y + d1;
    float x0f = floorf(px), y0f = floorf(py);
    float wx1 = px - x0f, wx0 = 1.0f - wx1;
    float wy1 = py - y0f, wy0 = 1.0f - wy1;

    float vc0[4], vc1[4], mm[4];
    float xs[4] = {x0f, x0f + 1.0f, x0f, x0f + 1.0f};
    float ys[4] = {y0f, y0f, y0f + 1.0f, y0f + 1.0f};
    #pragma unroll
    for (int q = 0; q < 4; q++) {
        float xi = xs[q], yi = ys[q];
        bool valid = (xi >= 0.f) && (xi <= (float)(WW - 1)) &&
                     (yi >= 0.f) && (yi <= (float)(HH - 1));
        float xc = fminf(fmaxf(xi, 0.f), (float)(WW - 1));
        float yc = fminf(fmaxf(yi, 0.f), (float)(HH - 1));
        int idx = (int)yc * WW + (int)xc;
        mm[q]  = valid ? 1.f : 0.f;
        vc0[q] = valid ? uf[idx] : 0.f;
        vc1[q] = valid ? uf[HW + idx] : 0.f;
    }
    float out0 = wy0 * (wx0 * vc0[0] + wx1 * vc0[1]) + wy1 * (wx0 * vc0[2] + wx1 * vc0[3]);
    float out1 = wy0 * (wx0 * vc1[0] + wx1 * vc1[1]) + wy1 * (wx0 * vc1[2] + wx1 * vc1[3]);
    float msk  = wy0 * (wx0 * mm[0] + wx1 * mm[1]) + wy1 * (wx0 * mm[2] + wx1 * mm[3]);
    float mask = (msk >= 1.0f) ? 1.f : 0.f;

    out[((size_t)(b * 2 + 0) * HH + y) * WW + x] = out0 * mask;
    out[((size_t)(b * 2 + 1) * HH + y) * WW + x] = out1 * mask;
    out[(size_t)BB * 2 * HW + ((size_t)b * HH + y) * WW + x] = 1.0f / (1.0f + expf(-cf));
}

// ---------------- launch -----------------------------------------------------
extern "C" void kernel_launch(void* const* d_in, const int* in_sizes, int n_in,
                              void* d_out, int out_size)
{
    const float* feats     = (const float*)d_in[0];
    const float* flow      = (const float*)d_in[1];
    const float* conf      = (const float*)d_in[2];
    const float* up_conf_w = (const float*)d_in[3];
    const float* up_flow_w = (const float*)d_in[4];
    const float* w1        = (const float*)d_in[5];
    const float* b1        = (const float*)d_in[6];
    const float* w2        = (const float*)d_in[7];
    const float* b2        = (const float*)d_in[8];
    const float* w3        = (const float*)d_in[9];
    const float* b3        = (const float*)d_in[10];
    const float* disp_w    = (const float*)d_in[11];
    const float* disp_b    = (const float*)d_in[12];
    const float* conf_w    = (const float*)d_in[13];
    const float* conf_b    = (const float*)d_in[14];
    float* out = (float*)d_out;

    float *xin, *x1, *x2, *x3;
    cudaGetSymbolAddress((void**)&xin, g_xin);
    cudaGetSymbolAddress((void**)&x1,  g_x1);
    cudaGetSymbolAddress((void**)&x2,  g_x2);
    cudaGetSymbolAddress((void**)&x3,  g_x3);

    deconv_kernel<<<(BB * 3 * HW + 255) / 256, 256>>>(flow, conf, up_flow_w, up_conf_w);
    corr_kernel<<<dim3(10, 10, BB), 512>>>(feats);
    conv3_kernel<50, 128, 2><<<dim3(5, 5, BB * 8), 256>>>(xin, w1, b1, x1);
    conv3_kernel<128, 64, 4><<<dim3(5, 5, BB * 4), 256>>>(x1, w2, b2, x2);
    conv3_kernel<64, 32, 4><<<dim3(5, 5, BB * 2), 256>>>(x2, w3, b3, x3);
    head_kernel<<<dim3(10, 10, BB), 256>>>(disp_w, disp_b, conf_w, conf_b, out);
}

// round 6
// speedup vs baseline: 1.4981x; 1.3006x over previous
#include <cuda_runtime.h>
#include <math.h>

#define BB 8
#define CC 128
#define HH 160
#define WW 160
#define HW (HH*WW)
#define Hh 80
#define Wh 80

typedef unsigned long long ull;

// ---------------- scratch ----------------------------------------------------
__device__ float g_upflow[BB*2*HW];
__device__ float g_xin[BB*50*HW];
__device__ float g_x1[BB*128*HW];
__device__ float g_x2[BB*64*HW];
__device__ float g_x3[BB*32*HW];

__device__ __forceinline__ float lrelu(float v) { return v > 0.f ? v : 0.1f * v; }

__device__ __forceinline__ void fma2(ull &d, ull a, ull b) {
    asm("fma.rn.f32x2 %0, %1, %2, %0;" : "+l"(d) : "l"(a), "l"(b));
}
__device__ __forceinline__ ull pk(float lo, float hi) {
    ull r;
    asm("mov.b64 %0, {%1, %2};" : "=l"(r) : "f"(lo), "f"(hi));
    return r;
}
__device__ __forceinline__ void upk(float &lo, float &hi, ull p) {
    asm("mov.b64 {%0, %1}, %2;" : "=f"(lo), "=f"(hi) : "l"(p));
}

__device__ __forceinline__ unsigned su(const void* p) {
    return (unsigned)__cvta_generic_to_shared(p);
}
__device__ __forceinline__ void cpa4(unsigned dst, const float* src, bool v) {
    int sz = v ? 4 : 0;
    asm volatile("cp.async.ca.shared.global [%0], [%1], 4, %2;" :: "r"(dst), "l"(src), "r"(sz));
}
#define CPCOMMIT asm volatile("cp.async.commit_group;")
#define CPWAIT(N) asm volatile("cp.async.wait_group %0;" :: "n"(N))

// ---------------- kernel 1: transposed-conv upsampling -----------------------
__global__ void deconv_kernel(const float* __restrict__ flow,
                              const float* __restrict__ conf,
                              const float* __restrict__ wf,
                              const float* __restrict__ wc)
{
    int i = blockIdx.x * blockDim.x + threadIdx.x;
    if (i >= BB * 3 * HW) return;
    int x  = i % WW;
    int y  = (i / WW) % HH;
    int ch = (i / HW) % 3;
    int b  = i / (3 * HW);

    const float* w;
    const float* in;
    if (ch < 2) { w = wf + ch * 16; in = flow + (b * 2 + ch) * (Hh * Wh); }
    else        { w = wc;           in = conf + b * (Hh * Wh); }

    float acc = 0.f;
    #pragma unroll
    for (int ky = 0; ky < 4; ky++) {
        int t = y + 1 - ky;
        if (t & 1) continue;
        int iy = t >> 1;
        if ((unsigned)iy >= Hh) continue;
        #pragma unroll
        for (int kx = 0; kx < 4; kx++) {
            int u = x + 1 - kx;
            if (u & 1) continue;
            int ix = u >> 1;
            if ((unsigned)ix >= Wh) continue;
            acc += in[iy * Wh + ix] * w[ky * 4 + kx];
        }
    }
    if (ch < 2) g_upflow[(b * 2 + ch) * HW + y * WW + x] = acc;
    else        g_xin[((size_t)b * 50 + 49) * HW + y * WW + x] = acc;
}

// ---------------- kernel 2: 7x7 dilated self-correlation ---------------------
__global__ __launch_bounds__(512) void corr_kernel(const float* __restrict__ feats)
{
    __shared__ float2 sm2[2][2][28][32];
    constexpr int TEL = 4 * 28 * 28;            // 3136
    constexpr int NJ  = (TEL + 511) / 512;      // 7
    constexpr int BUF = 2 * 28 * 32 * 2;        // floats per buffer (3584)

    int b   = blockIdx.z;
    int ty0 = blockIdx.y * 16, tx0 = blockIdx.x * 16;
    int tid = threadIdx.x;
    int lx  = tid & 15, ly = (tid >> 4) & 15, hd = tid >> 8;

    const float* f = feats + (size_t)b * 2 * CC * HW;

    // precompute prefetch offsets once
    int fgo[NJ], fso[NJ];
    unsigned vm = 0;
    #pragma unroll
    for (int j = 0; j < NJ; j++) {
        int e = tid + j * 512;
        fgo[j] = 0; fso[j] = 0;
        if (e < TEL) {
            int c  = e / 784;
            int rm = e - c * 784;
            int r  = rm / 28;
            int cc = rm - r * 28;
            int gy = ty0 + r - 6, gx = tx0 + cc - 6;
            bool v = ((unsigned)gy < HH) && ((unsigned)gx < WW);
            if (v) vm |= (1u << j);
            fgo[j] = c * HW + (v ? gy : 0) * WW + (v ? gx : 0);
            fso[j] = ((c >> 1) * 28 * 32 + r * 32 + cc) * 2 + (c & 1);
        }
    }
    unsigned su0 = su(&sm2[0][0][0][0]);

    ull acc2[25];
    #pragma unroll
    for (int d = 0; d < 25; d++) acc2[d] = 0ull;

    auto pre = [&](int c0, int s) {
        unsigned base = su0 + (unsigned)(s * BUF) * 4u;
        #pragma unroll
        for (int j = 0; j < NJ; j++) {
            int e = tid + j * 512;
            if (e < TEL)
                cpa4(base + 4u * (unsigned)fso[j], f + (size_t)c0 * HW + fgo[j], (vm >> j) & 1);
        }
    };

    pre(0, 0); CPCOMMIT;
    for (int ch = 0; ch < 32; ch++) {
        int s = ch & 1;
        if (ch < 31) { pre((ch + 1) * 4, s ^ 1); CPCOMMIT; CPWAIT(1); }
        else         { CPWAIT(0); }
        __syncthreads();
        #pragma unroll
        for (int pr = 0; pr < 2; pr++) {
            ull ctr = *(const ull*)&sm2[s][pr][ly + 6][lx + 6];
            if (hd == 0) {
                #pragma unroll
                for (int d = 0; d < 25; d++) {
                    int di = d / 7, dj = d % 7;
                    ull t = *(const ull*)&sm2[s][pr][ly + 2 * di][lx + 2 * dj];
                    fma2(acc2[d], ctr, t);
                }
            } else {
                #pragma unroll
                for (int d = 0; d < 25; d++) {
                    int di = (24 + d) / 7, dj = (24 + d) % 7;
                    ull t = *(const ull*)&sm2[s][pr][ly + 2 * di][lx + 2 * dj];
                    fma2(acc2[d], ctr, t);
                }
            }
        }
        __syncthreads();
    }

    int y = ty0 + ly, x = tx0 + lx;
    float* out = g_xin + (size_t)b * 50 * HW + y * WW + x;
    int D0 = hd * 24;
    #pragma unroll
    for (int d = 0; d < 25; d++) {
        float lo, hi;
        upk(lo, hi, acc2[d]);
        out[(size_t)(D0 + d) * HW] = lrelu(lo + hi) * (1.0f / 128.0f);
    }
}

// ---------------- kernel 3: 3x3 conv, dup-f32x2 smem, hoisted indexing -------
// 32x32 tile; 256 threads: ty=tid&31 (row), tx=(tid>>5)&1 (16px), og=tid>>6 (4oc)
template<int IC, int OC>
__global__ __launch_bounds__(256, 2) void conv3_kernel(const float* __restrict__ in,
                                                       const float* __restrict__ wt,
                                                       const float* __restrict__ bias,
                                                       float* __restrict__ out)
{
    constexpr int NIC   = 2;
    constexpr int NCH   = IC / NIC;
    constexpr int TELEM = NIC * 34 * 34;          // 2312
    constexpr int NJ    = (TELEM + 255) / 256;    // 10
    __shared__ __align__(16) float2 tin[2][NIC][34][38];
    __shared__ ull wsm[2][8][NIC][9];

    int tid = threadIdx.x;
    int ty = tid & 31;
    int tx = (tid >> 5) & 1;
    int og = tid >> 6;
    int bx = blockIdx.x * 32, by = blockIdx.y * 32;
    int bz = blockIdx.z;
    int ocg = bz % (OC / 16);
    int b   = bz / (OC / 16);

    const float* inb = in + (size_t)b * IC * HW;
    const float* wtb = wt + (size_t)(ocg * 16) * IC * 9;

    // ---- precompute tile element offsets (loop-invariant) ----
    int goff[NJ], soff[NJ];
    unsigned vm = 0;
    #pragma unroll
    for (int j = 0; j < NJ; j++) {
        int e = tid + j * 256;
        goff[j] = 0; soff[j] = 0;
        if (e < TELEM) {
            int cl = e / 1156;
            int rm = e - cl * 1156;
            int r  = rm / 34;
            int cc = rm - r * 34;
            int gy = by + r - 1, gx = bx + cc - 1;
            bool v = ((unsigned)gy < HH) && ((unsigned)gx < WW);
            if (v) vm |= (1u << j);
            goff[j] = cl * HW + (v ? gy : 0) * WW + (v ? gx : 0);
            soff[j] = (cl * 34 + r) * 38 + cc;
        }
    }
    // ---- precompute weight offsets ----
    bool wact = tid < 144;
    int wg0 = 0, wso = 0;
    if (wact) {
        int ocp = tid / 18;
        int rem = tid - ocp * 18;
        int cl = rem / 9, k = rem - cl * 9;
        wg0 = (ocp * 2) * IC * 9 + cl * 9 + k;
        wso = (ocp * NIC + cl) * 9 + k;
    }

    ull acc[2][16];
    #pragma unroll
    for (int o = 0; o < 2; o++)
        #pragma unroll
        for (int p = 0; p < 16; p++) acc[o][p] = 0ull;

    float tv[NJ];
    float wa, wb;

    auto ldt = [&](int ic0) {
        #pragma unroll
        for (int j = 0; j < NJ; j++) {
            int e = tid + j * 256;
            if (e < TELEM)
                tv[j] = ((vm >> j) & 1) ? __ldg(inb + (size_t)ic0 * HW + goff[j]) : 0.f;
        }
    };
    auto stt = [&](int s) {
        float2* tf = &tin[s][0][0][0];
        #pragma unroll
        for (int j = 0; j < NJ; j++) {
            int e = tid + j * 256;
            if (e < TELEM) tf[soff[j]] = make_float2(tv[j], tv[j]);
        }
    };
    auto ldw = [&](int ic0) {
        if (wact) {
            const float* p = wtb + wg0 + ic0 * 9;
            wa = p[0]; wb = p[IC * 9];
        }
    };
    auto stw = [&](int s) {
        if (wact) ((ull*)wsm)[s * 144 + wso] = pk(wa, wb);
    };

    ldt(0); ldw(0);
    stt(0); stw(0);

    for (int ch = 0; ch < NCH; ch++) {
        int s = ch & 1;
        if (ch + 1 < NCH) { ldt((ch + 1) * NIC); ldw((ch + 1) * NIC); }
        __syncthreads();

        #pragma unroll
        for (int cl = 0; cl < NIC; cl++) {
            #pragma unroll
            for (int ky = 0; ky < 3; ky++) {
                const ulonglong2* rp = (const ulonglong2*)&tin[s][cl][ty + ky][16 * tx];
                ull vv[18];
                #pragma unroll
                for (int i = 0; i < 9; i++) {
                    ulonglong2 t = rp[i];
                    vv[2 * i] = t.x; vv[2 * i + 1] = t.y;
                }
                #pragma unroll
                for (int o2 = 0; o2 < 2; o2++) {
                    const ull* wp = &wsm[s][og * 2 + o2][cl][ky * 3];
                    ull w0 = wp[0], w1 = wp[1], w2 = wp[2];
                    #pragma unroll
                    for (int p = 0; p < 16; p++) {
                        fma2(acc[o2][p], vv[p],     w0);
                        fma2(acc[o2][p], vv[p + 1], w1);
                        fma2(acc[o2][p], vv[p + 2], w2);
                    }
                }
            }
        }
        if (ch + 1 < NCH) { stt(s ^ 1); stw(s ^ 1); }
    }

    int y = by + ty, xb = bx + 16 * tx;
    #pragma unroll
    for (int o2 = 0; o2 < 2; o2++) {
        int oc0 = ocg * 16 + og * 4 + o2 * 2;
        float b0 = bias[oc0], b1 = bias[oc0 + 1];
        float r0[16], r1[16];
        #pragma unroll
        for (int p = 0; p < 16; p++) {
            float lo, hi;
            upk(lo, hi, acc[o2][p]);
            r0[p] = lrelu(lo + b0);
            r1[p] = lrelu(hi + b1);
        }
        float* op0 = out + ((size_t)(b * OC + oc0) * HH + y) * WW + xb;
        float* op1 = op0 + HW;
        #pragma unroll
        for (int q = 0; q < 4; q++) {
            *(float4*)(op0 + 4 * q) = make_float4(r0[4*q], r0[4*q+1], r0[4*q+2], r0[4*q+3]);
            *(float4*)(op1 + 4 * q) = make_float4(r1[4*q], r1[4*q+1], r1[4*q+2], r1[4*q+3]);
        }
    }
}

// ---------------- kernel 4: 5x5 heads + warp + sigmoid -----------------------
__global__ __launch_bounds__(256) void head_kernel(const float* __restrict__ disp_w,
                                                   const float* __restrict__ disp_b,
                                                   const float* __restrict__ conf_w,
                                                   const float* __restrict__ conf_b,
                                                   float* __restrict__ out)
{
    __shared__ float sm[8][20][20];
    __shared__ float wsm[3][32][25];
    int tid = threadIdx.x;
    int lx = tid & 15, ly = tid >> 4;
    int b = blockIdx.z;
    int ty0 = blockIdx.y * 16, tx0 = blockIdx.x * 16;

    for (int e = tid; e < 3 * 32 * 25; e += 256) {
        int o = e / (32 * 25);
        int rem = e % (32 * 25);
        float v = (o < 2) ? disp_w[o * 32 * 25 + rem] : conf_w[rem];
        wsm[o][rem / 25][rem % 25] = v;
    }

    const float* x3 = g_x3 + (size_t)b * 32 * HW;
    float d0 = 0.f, d1 = 0.f, cf = 0.f;

    for (int c0 = 0; c0 < 32; c0 += 8) {
        __syncthreads();
        for (int e = tid; e < 8 * 400; e += 256) {
            int cl = e / 400;
            int r  = (e % 400) / 20;
            int cc = e % 20;
            int gy = ty0 + r - 2, gx = tx0 + cc - 2;
            float v = 0.f;
            if ((unsigned)gy < HH && (unsigned)gx < WW)
                v = x3[(size_t)(c0 + cl) * HW + gy * WW + gx];
            sm[cl][r][cc] = v;
        }
        __syncthreads();
        #pragma unroll
        for (int cl = 0; cl < 8; cl++) {
            int ic = c0 + cl;
            #pragma unroll
            for (int ky = 0; ky < 5; ky++) {
                #pragma unroll
                for (int kx = 0; kx < 5; kx++) {
                    float v = sm[cl][ly + ky][lx + kx];
                    int k = ky * 5 + kx;
                    d0 += v * wsm[0][ic][k];
                    d1 += v * wsm[1][ic][k];
                    cf += v * wsm[2][ic][k];
                }
            }
        }
    }
    d0 += disp_b[0];
    d1 += disp_b[1];
    cf += conf_b[0];

    int y = ty0 + ly, x = tx0 + lx;

    const float* uf = g_upflow + (size_t)b * 2 * HW;
    float px = (float)x + d0;
    float py = (float)y + d1;
    float x0f = floorf(px), y0f = floorf(py);
    float wx1 = px - x0f, wx0 = 1.0f - wx1;
    float wy1 = py - y0f, wy0 = 1.0f - wy1;

    float vc0[4], vc1[4], mm[4];
    float xs[4] = {x0f, x0f + 1.0f, x0f, x0f + 1.0f};
    float ys[4] = {y0f, y0f, y0f + 1.0f, y0f + 1.0f};
    #pragma unroll
    for (int q = 0; q < 4; q++) {
        float xi = xs[q], yi = ys[q];
        bool valid = (xi >= 0.f) && (xi <= (float)(WW - 1)) &&
                     (yi >= 0.f) && (yi <= (float)(HH - 1));
        float xc = fminf(fmaxf(xi, 0.f), (float)(WW - 1));
        float yc = fminf(fmaxf(yi, 0.f), (float)(HH - 1));
        int idx = (int)yc * WW + (int)xc;
        mm[q]  = valid ? 1.f : 0.f;
        vc0[q] = valid ? uf[idx] : 0.f;
        vc1[q] = valid ? uf[HW + idx] : 0.f;
    }
    float out0 = wy0 * (wx0 * vc0[0] + wx1 * vc0[1]) + wy1 * (wx0 * vc0[2] + wx1 * vc0[3]);
    float out1 = wy0 * (wx0 * vc1[0] + wx1 * vc1[1]) + wy1 * (wx0 * vc1[2] + wx1 * vc1[3]);
    float msk  = wy0 * (wx0 * mm[0] + wx1 * mm[1]) + wy1 * (wx0 * mm[2] + wx1 * mm[3]);
    float mask = (msk >= 1.0f) ? 1.f : 0.f;

    out[((size_t)(b * 2 + 0) * HH + y) * WW + x] = out0 * mask;
    out[((size_t)(b * 2 + 1) * HH + y) * WW + x] = out1 * mask;
    out[(size_t)BB * 2 * HW + ((size_t)b * HH + y) * WW + x] = 1.0f / (1.0f + expf(-cf));
}

// ---------------- launch -----------------------------------------------------
extern "C" void kernel_launch(void* const* d_in, const int* in_sizes, int n_in,
                              void* d_out, int out_size)
{
    const float* feats     = (const float*)d_in[0];
    const float* flow      = (const float*)d_in[1];
    const float* conf      = (const float*)d_in[2];
    const float* up_conf_w = (const float*)d_in[3];
    const float* up_flow_w = (const float*)d_in[4];
    const float* w1        = (const float*)d_in[5];
    const float* b1        = (const float*)d_in[6];
    const float* w2        = (const float*)d_in[7];
    const float* b2        = (const float*)d_in[8];
    const float* w3        = (const float*)d_in[9];
    const float* b3        = (const float*)d_in[10];
    const float* disp_w    = (const float*)d_in[11];
    const float* disp_b    = (const float*)d_in[12];
    const float* conf_w    = (const float*)d_in[13];
    const float* conf_b    = (const float*)d_in[14];
    float* out = (float*)d_out;

    float *xin, *x1, *x2, *x3;
    cudaGetSymbolAddress((void**)&xin, g_xin);
    cudaGetSymbolAddress((void**)&x1,  g_x1);
    cudaGetSymbolAddress((void**)&x2,  g_x2);
    cudaGetSymbolAddress((void**)&x3,  g_x3);

    deconv_kernel<<<(BB * 3 * HW + 255) / 256, 256>>>(flow, conf, up_flow_w, up_conf_w);
    corr_kernel<<<dim3(10, 10, BB), 512>>>(feats);
    conv3_kernel<50, 128><<<dim3(5, 5, BB * 8), 256>>>(xin, w1, b1, x1);
    conv3_kernel<128, 64><<<dim3(5, 5, BB * 4), 256>>>(x1, w2, b2, x2);
    conv3_kernel<64, 32><<<dim3(5, 5, BB * 2), 256>>>(x2, w3, b3, x3);
    head_kernel<<<dim3(10, 10, BB), 256>>>(disp_w, disp_b, conf_w, conf_b, out);
}